// round 1
// baseline (speedup 1.0000x reference)
#include <cuda_runtime.h>
#include <math.h>

#define BB   64
#define HH   1024
#define ED   1024
#define VV   32000
#define TT   50
#define G4   4096
#define START_INDEX 1

// ---------------- device-resident state (no allocations) ----------------
__device__ float g_x[BB * ED];        // gathered embedding rows
__device__ float g_h[BB * HH];        // hidden state
__device__ float g_c[BB * HH];        // cell state
__device__ float g_gx[BB * G4];       // x @ W_ih^T
__device__ float g_gh[BB * G4];       // h @ W_hh^T
__device__ float g_logits[(size_t)BB * VV];
__device__ int   g_last[BB];

// ---------------- init: h = hidden, c = 0, last = START ----------------
__global__ void init_kernel(const float* __restrict__ hidden) {
    int i = blockIdx.x * blockDim.x + threadIdx.x;
    if (i < BB * HH) {
        g_h[i] = hidden[i];
        g_c[i] = 0.0f;
    }
    if (i < BB) g_last[i] = START_INDEX;
}

// ---------------- embedding gather: g_x[b,:] = embedding[last[b],:] ----
__global__ void embed_kernel(const float* __restrict__ emb) {
    int b = blockIdx.x;
    int row = g_last[b];
    const float4* src = (const float4*)(emb + (size_t)row * ED);
    float4* dst = (float4*)(g_x + (size_t)b * ED);
    dst[threadIdx.x] = src[threadIdx.x];   // 256 threads * 4 floats = 1024
}

// ---------------- generic skinny GEMM: C[64xN] = A[64xK] @ B[NxK]^T ----
// blockIdx.y selects (A0,B0,C0) or (A1,B1,C1) so gates can run both
// halves in one launch. BM=64, BN=64, BK=64, 256 threads, 4x4 microtile.
__global__ void __launch_bounds__(256) gemm64_kernel(
    const float* __restrict__ A0, const float* __restrict__ Bm0, float* __restrict__ C0,
    const float* __restrict__ A1, const float* __restrict__ Bm1, float* __restrict__ C1,
    int N, int K)
{
    const float* A  = A0;
    const float* Bm = Bm0;
    float*       C  = C0;
    if (blockIdx.y == 1) { A = A1; Bm = Bm1; C = C1; }

    __shared__ float As[64][68];   // [k][m], padded for alignment
    __shared__ float Bs[64][68];   // [k][n]

    const int n0 = blockIdx.x * 64;
    const int tn = threadIdx.x & 15;   // 0..15 -> n micro
    const int tm = threadIdx.x >> 4;   // 0..15 -> m micro

    float acc[4][4] = {};

    for (int k0 = 0; k0 < K; k0 += 64) {
        // Fill tiles: 4096 elements each, 16 per thread, coalesced on k.
        #pragma unroll
        for (int l = 0; l < 16; l++) {
            int idx = threadIdx.x + l * 256;
            int r   = idx >> 6;    // row (m for A, n for B)
            int kk  = idx & 63;
            As[kk][r] = A[(size_t)r * K + k0 + kk];
            Bs[kk][r] = Bm[(size_t)(n0 + r) * K + k0 + kk];
        }
        __syncthreads();

        #pragma unroll
        for (int kk = 0; kk < 64; kk++) {
            float4 av = *(const float4*)(&As[kk][tm * 4]);
            float4 bv = *(const float4*)(&Bs[kk][tn * 4]);
            float am[4] = {av.x, av.y, av.z, av.w};
            float bn[4] = {bv.x, bv.y, bv.z, bv.w};
            #pragma unroll
            for (int i = 0; i < 4; i++)
                #pragma unroll
                for (int j = 0; j < 4; j++)
                    acc[i][j] += am[i] * bn[j];
        }
        __syncthreads();
    }

    #pragma unroll
    for (int i = 0; i < 4; i++)
        #pragma unroll
        for (int j = 0; j < 4; j++)
            C[(size_t)(tm * 4 + i) * N + n0 + tn * 4 + j] = acc[i][j];
}

// ---------------- LSTM cell elementwise -------------------------------
__device__ __forceinline__ float sigm(float x) { return 1.0f / (1.0f + expf(-x)); }

__global__ void cell_kernel(const float* __restrict__ b_ih,
                            const float* __restrict__ b_hh) {
    int idx = blockIdx.x * blockDim.x + threadIdx.x;   // over B*H
    if (idx >= BB * HH) return;
    int b = idx >> 10;        // H = 1024
    int n = idx & 1023;
    const float* gx = g_gx + (size_t)b * G4;
    const float* gh = g_gh + (size_t)b * G4;

    float ig = gx[n]            + gh[n]            + b_ih[n]            + b_hh[n];
    float fg = gx[HH + n]       + gh[HH + n]       + b_ih[HH + n]       + b_hh[HH + n];
    float gg = gx[2 * HH + n]   + gh[2 * HH + n]   + b_ih[2 * HH + n]   + b_hh[2 * HH + n];
    float og = gx[3 * HH + n]   + gh[3 * HH + n]   + b_ih[3 * HH + n]   + b_hh[3 * HH + n];

    float c  = g_c[idx];
    float cn = sigm(fg) * c + sigm(ig) * tanhf(gg);
    float hn = sigm(og) * tanhf(cn);
    g_c[idx] = cn;
    g_h[idx] = hn;
}

// ---------------- softmax + first-index argmax + output write ---------
__global__ void __launch_bounds__(1024) softmax_kernel(
    const float* __restrict__ b_out, float* __restrict__ out, int t)
{
    const int b   = blockIdx.x;
    const int tid = threadIdx.x;
    const float* lrow = g_logits + (size_t)b * VV;

    __shared__ float smax[1024];
    __shared__ int   sidx[1024];
    __shared__ float ssum[1024];

    // pass 1: max with first-occurrence index (strict > keeps earliest)
    float mx = -3.4e38f;
    int   mi = 0;
    for (int v = tid; v < VV; v += 1024) {
        float l = lrow[v] + b_out[v];
        if (l > mx) { mx = l; mi = v; }
    }
    smax[tid] = mx; sidx[tid] = mi;
    __syncthreads();
    for (int s = 512; s > 0; s >>= 1) {
        if (tid < s) {
            float om = smax[tid + s]; int oi = sidx[tid + s];
            if (om > smax[tid] || (om == smax[tid] && oi < sidx[tid])) {
                smax[tid] = om; sidx[tid] = oi;
            }
        }
        __syncthreads();
    }
    float rowmax = smax[0];
    int   pred   = sidx[0];

    // pass 2: sum of exp
    float acc = 0.0f;
    for (int v = tid; v < VV; v += 1024)
        acc += expf(lrow[v] + b_out[v] - rowmax);
    ssum[tid] = acc;
    __syncthreads();
    for (int s = 512; s > 0; s >>= 1) {
        if (tid < s) ssum[tid] += ssum[tid + s];
        __syncthreads();
    }
    float inv = 1.0f / ssum[0];

    // pass 3: write probabilities out[b, t, :]
    float* orow = out + ((size_t)b * TT + t) * VV;
    for (int v = tid; v < VV; v += 1024)
        orow[v] = expf(lrow[v] + b_out[v] - rowmax) * inv;

    if (tid == 0) {
        g_last[b] = pred;
        // predictions block sits after the probabilities block: [B, T]
        out[(size_t)BB * TT * VV + (size_t)b * TT + t] = (float)pred;
    }
}

// ---------------- launch ----------------------------------------------
extern "C" void kernel_launch(void* const* d_in, const int* in_sizes, int n_in,
                              void* d_out, int out_size) {
    const float* hidden    = (const float*)d_in[0];
    const float* embedding = (const float*)d_in[1];
    const float* W_ih      = (const float*)d_in[2];
    const float* W_hh      = (const float*)d_in[3];
    const float* b_ih      = (const float*)d_in[4];
    const float* b_hh      = (const float*)d_in[5];
    const float* W_out     = (const float*)d_in[6];
    const float* b_out     = (const float*)d_in[7];
    float* out = (float*)d_out;

    float *px, *ph, *pgx, *pgh, *plog;
    cudaGetSymbolAddress((void**)&px,   g_x);
    cudaGetSymbolAddress((void**)&ph,   g_h);
    cudaGetSymbolAddress((void**)&pgx,  g_gx);
    cudaGetSymbolAddress((void**)&pgh,  g_gh);
    cudaGetSymbolAddress((void**)&plog, g_logits);

    init_kernel<<<(BB * HH + 255) / 256, 256>>>(hidden);

    for (int t = 0; t < TT; t++) {
        embed_kernel<<<BB, 256>>>(embedding);

        // gates: y=0 -> x @ W_ih^T, y=1 -> h @ W_hh^T   (N=4096, K=1024)
        gemm64_kernel<<<dim3(G4 / 64, 2), 256>>>(
            px, W_ih, pgx,
            ph, W_hh, pgh,
            G4, HH);

        cell_kernel<<<(BB * HH + 255) / 256, 256>>>(b_ih, b_hh);

        // logits: h @ W_out^T   (N=32000, K=1024)
        gemm64_kernel<<<dim3(VV / 64, 1), 256>>>(
            ph, W_out, plog,
            ph, W_out, plog,
            VV, HH);

        softmax_kernel<<<BB, 1024>>>(b_out, out, t);
    }
}

// round 2
// speedup vs baseline: 1.1224x; 1.1224x over previous
#include <cuda_runtime.h>
#include <math.h>

#define BB   64
#define HH   1024
#define ED   1024
#define VV   32000
#define TT   50
#define G4   4096
#define START_INDEX 1

#define BM 64
#define BN 128
#define BK 32
#define SPLITK 8
#define KC_GATES ((2 * HH) / SPLITK)   // 256

typedef unsigned long long ull;

// ---------------- device-resident state (no allocations) ----------------
__device__ float g_h[BB * HH];                    // hidden state
__device__ float g_c[BB * HH];                    // cell state
__device__ float g_gp[SPLITK][BB * G4];           // split-K partial gate sums
__device__ float g_logits[(size_t)BB * VV];
__device__ int   g_last[BB];

// ---------------- init: h = hidden, c = 0, last = START ----------------
__global__ void init_kernel(const float* __restrict__ hidden) {
    int i = blockIdx.x * blockDim.x + threadIdx.x;
    if (i < BB * HH) {
        g_h[i] = hidden[i];
        g_c[i] = 0.0f;
    }
    if (i < BB) g_last[i] = START_INDEX;
}

// ---------------- packed f32x2 helpers ---------------------------------
__device__ __forceinline__ ull pk2(float x, float y) {
    ull r;
    asm("mov.b64 %0, {%1, %2};" : "=l"(r) : "f"(x), "f"(y));
    return r;
}
__device__ __forceinline__ void ffma2(ull& d, ull a, ull b) {
    asm("fma.rn.f32x2 %0, %1, %2, %0;" : "+l"(d) : "l"(a), "l"(b));
}
union U2 { ull u; float2 f; };

// ---------------- GEMM: C[64 x N] = A[64 x K] @ W[N x K]^T -------------
// CAT mode: A = [embedding[last], h] (K=2048), W = [W_ih | W_hh], split-K
//           over blockIdx.y (8 chunks of 256), partials into Cout chunks.
// Plain:    A = g_h (K=1024), W = W_out, bias added, single output.
// 256 threads, BM=64, BN=128, BK=32, 4x8 microtile via fma.rn.f32x2.
template<bool CAT>
__global__ void __launch_bounds__(256, 2) gemm_kernel(
    const float* __restrict__ emb,
    const float* __restrict__ W0,
    const float* __restrict__ W1,
    const float* __restrict__ bias,
    float* __restrict__ Cout,
    int N, int Kc)
{
    __shared__ float As[BK][68];    // [k][m], swizzled m
    __shared__ float Bs[BK][132];   // [k][n], swizzled n

    const int t  = threadIdx.x;
    const int n0 = blockIdx.x * BN;
    const int kbase = CAT ? blockIdx.y * Kc : 0;
    float* C = Cout + (CAT ? (size_t)blockIdx.y * BM * N : 0);

    // ---- global load thread mapping ----
    const int ar = t >> 2;            // A row 0..63
    const int ak = (t & 3) * 8;       // A k-offset (2 float4)
    const int bn = t >> 1;            // B row (n) 0..127
    const int bk = (t & 1) * 16;      // B k-offset (4 float4)

    const float* Aptr;
    if (CAT) {
        if (kbase < HH)
            Aptr = emb + (size_t)g_last[ar] * ED + kbase;
        else
            Aptr = g_h + (size_t)ar * HH + (kbase - HH);
    } else {
        Aptr = g_h + (size_t)ar * HH;
    }
    Aptr += ak;

    const float* Wp;
    if (CAT) {
        if (kbase < HH) Wp = W0 + (size_t)(n0 + bn) * HH + kbase;
        else            Wp = W1 + (size_t)(n0 + bn) * HH + (kbase - HH);
    } else {
        Wp = W0 + (size_t)(n0 + bn) * HH;
    }
    Wp += bk;

    const int aswz = ar ^ ((t & 3) * 8);
    const int bswz = bn ^ ((t & 1) * 16);

    // ---- compute thread mapping ----
    const int tn = t & 15;            // n micro (8 cols)
    const int tm = t >> 4;            // m micro (4 rows)

    ull acc[4][4];
    #pragma unroll
    for (int i = 0; i < 4; i++)
        #pragma unroll
        for (int j = 0; j < 4; j++) acc[i][j] = 0ull;

    float4 ra0, ra1, rb0, rb1, rb2, rb3;

    // initial tile load
    ra0 = *(const float4*)(Aptr + 0);
    ra1 = *(const float4*)(Aptr + 4);
    rb0 = *(const float4*)(Wp + 0);
    rb1 = *(const float4*)(Wp + 4);
    rb2 = *(const float4*)(Wp + 8);
    rb3 = *(const float4*)(Wp + 12);

    for (int k0 = 0; k0 < Kc; k0 += BK) {
        // stage current regs -> smem
        {
            const float* a0 = &ra0.x;
            const float* a1 = &ra1.x;
            #pragma unroll
            for (int e = 0; e < 4; e++) {
                As[ak + e][aswz]     = a0[e];
                As[ak + 4 + e][aswz] = a1[e];
            }
            const float* b0 = &rb0.x; const float* b1 = &rb1.x;
            const float* b2 = &rb2.x; const float* b3 = &rb3.x;
            #pragma unroll
            for (int e = 0; e < 4; e++) {
                Bs[bk + e][bswz]      = b0[e];
                Bs[bk + 4 + e][bswz]  = b1[e];
                Bs[bk + 8 + e][bswz]  = b2[e];
                Bs[bk + 12 + e][bswz] = b3[e];
            }
        }
        __syncthreads();

        // prefetch next tile into regs
        const bool haveNext = (k0 + BK < Kc);
        if (haveNext) {
            int kn = k0 + BK;
            ra0 = *(const float4*)(Aptr + kn);
            ra1 = *(const float4*)(Aptr + kn + 4);
            rb0 = *(const float4*)(Wp + kn);
            rb1 = *(const float4*)(Wp + kn + 4);
            rb2 = *(const float4*)(Wp + kn + 8);
            rb3 = *(const float4*)(Wp + kn + 12);
        }

        // compute BK=32 k-steps
        #pragma unroll
        for (int kk = 0; kk < BK; kk++) {
            const int asw = ((kk >> 3) & 3) * 8;
            const int bsw = ((kk >> 4) & 1) * 16;
            float4 av  = *(const float4*)&As[kk][(tm * 4) ^ asw];
            float4 bv0 = *(const float4*)&Bs[kk][(tn * 8) ^ bsw];
            float4 bv1 = *(const float4*)&Bs[kk][((tn * 8) ^ bsw) + 4];

            ull ap0 = pk2(av.x, av.x);
            ull ap1 = pk2(av.y, av.y);
            ull ap2 = pk2(av.z, av.z);
            ull ap3 = pk2(av.w, av.w);
            ull bp0 = pk2(bv0.x, bv0.y);
            ull bp1 = pk2(bv0.z, bv0.w);
            ull bp2 = pk2(bv1.x, bv1.y);
            ull bp3 = pk2(bv1.z, bv1.w);

            ffma2(acc[0][0], ap0, bp0); ffma2(acc[0][1], ap0, bp1);
            ffma2(acc[0][2], ap0, bp2); ffma2(acc[0][3], ap0, bp3);
            ffma2(acc[1][0], ap1, bp0); ffma2(acc[1][1], ap1, bp1);
            ffma2(acc[1][2], ap1, bp2); ffma2(acc[1][3], ap1, bp3);
            ffma2(acc[2][0], ap2, bp0); ffma2(acc[2][1], ap2, bp1);
            ffma2(acc[2][2], ap2, bp2); ffma2(acc[2][3], ap2, bp3);
            ffma2(acc[3][0], ap3, bp0); ffma2(acc[3][1], ap3, bp1);
            ffma2(acc[3][2], ap3, bp2); ffma2(acc[3][3], ap3, bp3);
        }
        __syncthreads();
    }

    // ---- epilogue ----
    float4 bz0 = make_float4(0.f, 0.f, 0.f, 0.f);
    float4 bz1 = bz0;
    if (!CAT && bias) {
        bz0 = *(const float4*)(bias + n0 + tn * 8);
        bz1 = *(const float4*)(bias + n0 + tn * 8 + 4);
    }

    #pragma unroll
    for (int i = 0; i < 4; i++) {
        U2 u0, u1, u2, u3;
        u0.u = acc[i][0]; u1.u = acc[i][1];
        u2.u = acc[i][2]; u3.u = acc[i][3];
        float4 lo = make_float4(u0.f.x + bz0.x, u0.f.y + bz0.y,
                                u1.f.x + bz0.z, u1.f.y + bz0.w);
        float4 hi = make_float4(u2.f.x + bz1.x, u2.f.y + bz1.y,
                                u3.f.x + bz1.z, u3.f.y + bz1.w);
        float* crow = C + (size_t)(tm * 4 + i) * N + n0 + tn * 8;
        *(float4*)(crow)     = lo;
        *(float4*)(crow + 4) = hi;
    }
}

// ---------------- LSTM cell: sum split-K partials + elementwise --------
__global__ void __launch_bounds__(256) cell_kernel(
    const float* __restrict__ b_ih, const float* __restrict__ b_hh)
{
    int idx4 = blockIdx.x * blockDim.x + threadIdx.x;   // over BB*HH/4
    if (idx4 >= BB * HH / 4) return;
    int b  = idx4 >> 8;           // HH/4 = 256 quads per row
    int n  = (idx4 & 255) * 4;

    float4 gq[4];                  // i, f, g, o (each 4 lanes)
    #pragma unroll
    for (int q = 0; q < 4; q++) {
        float4 s = make_float4(0.f, 0.f, 0.f, 0.f);
        size_t off = (size_t)b * G4 + q * HH + n;
        #pragma unroll
        for (int p = 0; p < SPLITK; p++) {
            float4 v = *(const float4*)(&g_gp[p][off]);
            s.x += v.x; s.y += v.y; s.z += v.z; s.w += v.w;
        }
        float4 bi = *(const float4*)(b_ih + q * HH + n);
        float4 bh = *(const float4*)(b_hh + q * HH + n);
        s.x += bi.x + bh.x; s.y += bi.y + bh.y;
        s.z += bi.z + bh.z; s.w += bi.w + bh.w;
        gq[q] = s;
    }

    float4 c = *(const float4*)(&g_c[(size_t)b * HH + n]);
    float4 cn, hn;
    #pragma unroll
    for (int e = 0; e < 4; e++) {
        float ig = (&gq[0].x)[e];
        float fg = (&gq[1].x)[e];
        float gg = (&gq[2].x)[e];
        float og = (&gq[3].x)[e];
        float cv = (&c.x)[e];
        float si = 1.0f / (1.0f + expf(-ig));
        float sf = 1.0f / (1.0f + expf(-fg));
        float so = 1.0f / (1.0f + expf(-og));
        float cnew = sf * cv + si * tanhf(gg);
        (&cn.x)[e] = cnew;
        (&hn.x)[e] = so * tanhf(cnew);
    }
    *(float4*)(&g_c[(size_t)b * HH + n]) = cn;
    *(float4*)(&g_h[(size_t)b * HH + n]) = hn;
}

// ---------------- softmax + first-index argmax + output write ----------
__global__ void __launch_bounds__(1024) softmax_kernel(float* __restrict__ out, int t)
{
    const int b   = blockIdx.x;
    const int tid = threadIdx.x;
    const float4* lrow4 = (const float4*)(g_logits + (size_t)b * VV);
    const int NV4 = VV / 4;   // 8000

    __shared__ float smax[1024];
    __shared__ int   sidx[1024];
    __shared__ float ssum[1024];

    // pass 1: max with first-occurrence index
    float mx = -3.4e38f;
    int   mi = 0;
    for (int v = tid; v < NV4; v += 1024) {
        float4 l = lrow4[v];
        #pragma unroll
        for (int e = 0; e < 4; e++) {
            float le = (&l.x)[e];
            if (le > mx) { mx = le; mi = v * 4 + e; }
        }
    }
    smax[tid] = mx; sidx[tid] = mi;
    __syncthreads();
    for (int s = 512; s > 0; s >>= 1) {
        if (tid < s) {
            float om = smax[tid + s]; int oi = sidx[tid + s];
            if (om > smax[tid] || (om == smax[tid] && oi < sidx[tid])) {
                smax[tid] = om; sidx[tid] = oi;
            }
        }
        __syncthreads();
    }
    const float rowmax = smax[0];
    const int   pred   = sidx[0];

    // pass 2: sum of exp
    float acc = 0.0f;
    for (int v = tid; v < NV4; v += 1024) {
        float4 l = lrow4[v];
        acc += __expf(l.x - rowmax) + __expf(l.y - rowmax)
             + __expf(l.z - rowmax) + __expf(l.w - rowmax);
    }
    ssum[tid] = acc;
    __syncthreads();
    for (int s = 512; s > 0; s >>= 1) {
        if (tid < s) ssum[tid] += ssum[tid + s];
        __syncthreads();
    }
    const float inv = 1.0f / ssum[0];

    // pass 3: write probabilities out[b, t, :]
    float4* orow4 = (float4*)(out + ((size_t)b * TT + t) * VV);
    for (int v = tid; v < NV4; v += 1024) {
        float4 l = lrow4[v];
        float4 o;
        o.x = __expf(l.x - rowmax) * inv;
        o.y = __expf(l.y - rowmax) * inv;
        o.z = __expf(l.z - rowmax) * inv;
        o.w = __expf(l.w - rowmax) * inv;
        orow4[v] = o;
    }

    if (tid == 0) {
        g_last[b] = pred;
        out[(size_t)BB * TT * VV + (size_t)b * TT + t] = (float)pred;
    }
}

// ---------------- launch ------------------------------------------------
extern "C" void kernel_launch(void* const* d_in, const int* in_sizes, int n_in,
                              void* d_out, int out_size) {
    const float* hidden    = (const float*)d_in[0];
    const float* embedding = (const float*)d_in[1];
    const float* W_ih      = (const float*)d_in[2];
    const float* W_hh      = (const float*)d_in[3];
    const float* b_ih      = (const float*)d_in[4];
    const float* b_hh      = (const float*)d_in[5];
    const float* W_out     = (const float*)d_in[6];
    const float* b_out     = (const float*)d_in[7];
    float* out = (float*)d_out;

    float *pgp, *plog;
    cudaGetSymbolAddress((void**)&pgp,  g_gp);
    cudaGetSymbolAddress((void**)&plog, g_logits);

    init_kernel<<<(BB * HH + 255) / 256, 256>>>(hidden);

    for (int t = 0; t < TT; t++) {
        // gates: C_part[s] = A_cat[:, s*256:(s+1)*256] @ Wcat^T chunk
        gemm_kernel<true><<<dim3(G4 / BN, SPLITK), 256>>>(
            embedding, W_ih, W_hh, nullptr, pgp, G4, KC_GATES);

        cell_kernel<<<(BB * HH / 4 + 255) / 256, 256>>>(b_ih, b_hh);

        // logits: h @ W_out^T + b_out
        gemm_kernel<false><<<dim3(VV / BN, 1), 256>>>(
            embedding, W_out, nullptr, b_out, plog, VV, HH);

        softmax_kernel<<<BB, 1024>>>(out, t);
    }
}

// round 3
// speedup vs baseline: 1.2810x; 1.1413x over previous
#include <cuda_runtime.h>
#include <math.h>

#define BB   64
#define HH   1024
#define ED   1024
#define VV   32000
#define TT   50
#define G4   4096
#define START_INDEX 1

#define BM 64
#define BN 128
#define BK 32
#define SPLITK 8
#define KC_GATES ((2 * HH) / SPLITK)   // 256

typedef unsigned long long ull;

// ---------------- device-resident state (no allocations) ----------------
__device__ float g_h[BB * HH];                    // hidden state
__device__ float g_c[BB * HH];                    // cell state
__device__ float g_gp[SPLITK][BB * G4];           // split-K partial gate sums
__device__ float g_logits[(size_t)BB * VV];
__device__ int   g_last[BB];

// ---------------- init: h = hidden, c = 0, last = START ----------------
__global__ void init_kernel(const float* __restrict__ hidden) {
    int i = blockIdx.x * blockDim.x + threadIdx.x;
    if (i < BB * HH) {
        g_h[i] = hidden[i];
        g_c[i] = 0.0f;
    }
    if (i < BB) g_last[i] = START_INDEX;
}

// ---------------- packed f32x2 helpers ---------------------------------
__device__ __forceinline__ ull pk2(float x, float y) {
    ull r;
    asm("mov.b64 %0, {%1, %2};" : "=l"(r) : "f"(x), "f"(y));
    return r;
}
__device__ __forceinline__ void ffma2(ull& d, ull a, ull b) {
    asm("fma.rn.f32x2 %0, %1, %2, %0;" : "+l"(d) : "l"(a), "l"(b));
}
union U2 { ull u; float2 f; };

// ---------------- GEMM: C[64 x N] = A[64 x K] @ W[N x K]^T -------------
// CAT mode: A = [embedding[last], h] (K=2048), W = [W_ih | W_hh], split-K
//           over blockIdx.y (8 chunks of 256), partials into Cout chunks.
// Plain:    A = g_h (K=1024), W = W_out, bias added, single output.
// 256 threads, BM=64, BN=128, BK=32.
// A is stored SPLATTED in smem (ull = (a,a)); B pairs are read as raw
// ulonglong2 -> every FFMA2 operand comes straight from LDS, zero MOVs.
// Thread (tm,tn) computes rows tm*4..+3, cols {tn*4..+3} and {64+tn*4..+3}.
template<bool CAT>
__global__ void __launch_bounds__(256, 2) gemm_kernel(
    const float* __restrict__ emb,
    const float* __restrict__ W0,
    const float* __restrict__ W1,
    const float* __restrict__ bias,
    float* __restrict__ Cout,
    int N, int Kc)
{
    __shared__ ull   As2[BK][66];    // splatted A: [k][m], (a,a)
    __shared__ float Bs[BK][132];    // [k][n]

    const int t  = threadIdx.x;
    const int n0 = blockIdx.x * BN;
    const int kbase = CAT ? blockIdx.y * Kc : 0;
    float* C = Cout + (CAT ? (size_t)blockIdx.y * BM * N : 0);

    // ---- global load thread mapping ----
    const int ar = t >> 2;            // A row 0..63
    const int ak = (t & 3) * 8;       // A k-offset (2 float4)
    const int bn = t >> 1;            // B row (n) 0..127
    const int bk = (t & 1) * 16;      // B k-offset (4 float4)

    const float* Aptr;
    if (CAT) {
        if (kbase < HH)
            Aptr = emb + (size_t)g_last[ar] * ED + kbase;
        else
            Aptr = g_h + (size_t)ar * HH + (kbase - HH);
    } else {
        Aptr = g_h + (size_t)ar * HH;
    }
    Aptr += ak;

    const float* Wp;
    if (CAT) {
        if (kbase < HH) Wp = W0 + (size_t)(n0 + bn) * HH + kbase;
        else            Wp = W1 + (size_t)(n0 + bn) * HH + (kbase - HH);
    } else {
        Wp = W0 + (size_t)(n0 + bn) * HH;
    }
    Wp += bk;

    // ---- compute thread mapping ----
    const int tn = t & 15;            // n micro: cols tn*4 and 64+tn*4
    const int tm = t >> 4;            // m micro: rows tm*4..+3

    ull acc[4][4];                    // [mi][nj]: nj 0,1 -> low chunk pairs,
    #pragma unroll                    //           nj 2,3 -> high chunk pairs
    for (int i = 0; i < 4; i++)
        #pragma unroll
        for (int j = 0; j < 4; j++) acc[i][j] = 0ull;

    float4 ra0, ra1, rb0, rb1, rb2, rb3;

    // initial tile load
    ra0 = *(const float4*)(Aptr + 0);
    ra1 = *(const float4*)(Aptr + 4);
    rb0 = *(const float4*)(Wp + 0);
    rb1 = *(const float4*)(Wp + 4);
    rb2 = *(const float4*)(Wp + 8);
    rb3 = *(const float4*)(Wp + 12);

    for (int k0 = 0; k0 < Kc; k0 += BK) {
        // stage current regs -> smem (A gets splatted here, once per tile)
        {
            const float* a0 = &ra0.x;
            const float* a1 = &ra1.x;
            #pragma unroll
            for (int e = 0; e < 4; e++) {
                As2[ak + e][ar]     = pk2(a0[e], a0[e]);
                As2[ak + 4 + e][ar] = pk2(a1[e], a1[e]);
            }
            const float* b0 = &rb0.x; const float* b1 = &rb1.x;
            const float* b2 = &rb2.x; const float* b3 = &rb3.x;
            #pragma unroll
            for (int e = 0; e < 4; e++) {
                Bs[bk + e][bn]      = b0[e];
                Bs[bk + 4 + e][bn]  = b1[e];
                Bs[bk + 8 + e][bn]  = b2[e];
                Bs[bk + 12 + e][bn] = b3[e];
            }
        }
        __syncthreads();

        // prefetch next tile into regs
        if (k0 + BK < Kc) {
            int kn = k0 + BK;
            ra0 = *(const float4*)(Aptr + kn);
            ra1 = *(const float4*)(Aptr + kn + 4);
            rb0 = *(const float4*)(Wp + kn);
            rb1 = *(const float4*)(Wp + kn + 4);
            rb2 = *(const float4*)(Wp + kn + 8);
            rb3 = *(const float4*)(Wp + kn + 12);
        }

        // compute BK=32 k-steps: per kk = 4 LDS.128 + 16 FFMA2, no MOVs
        #pragma unroll 16
        for (int kk = 0; kk < BK; kk++) {
            ulonglong2 a01 = *(const ulonglong2*)&As2[kk][tm * 4];
            ulonglong2 a23 = *(const ulonglong2*)&As2[kk][tm * 4 + 2];
            ulonglong2 bL  = *(const ulonglong2*)&Bs[kk][tn * 4];
            ulonglong2 bH  = *(const ulonglong2*)&Bs[kk][64 + tn * 4];

            ffma2(acc[0][0], a01.x, bL.x); ffma2(acc[0][1], a01.x, bL.y);
            ffma2(acc[0][2], a01.x, bH.x); ffma2(acc[0][3], a01.x, bH.y);
            ffma2(acc[1][0], a01.y, bL.x); ffma2(acc[1][1], a01.y, bL.y);
            ffma2(acc[1][2], a01.y, bH.x); ffma2(acc[1][3], a01.y, bH.y);
            ffma2(acc[2][0], a23.x, bL.x); ffma2(acc[2][1], a23.x, bL.y);
            ffma2(acc[2][2], a23.x, bH.x); ffma2(acc[2][3], a23.x, bH.y);
            ffma2(acc[3][0], a23.y, bL.x); ffma2(acc[3][1], a23.y, bL.y);
            ffma2(acc[3][2], a23.y, bH.x); ffma2(acc[3][3], a23.y, bH.y);
        }
        __syncthreads();
    }

    // ---- epilogue ----
    float4 bzL = make_float4(0.f, 0.f, 0.f, 0.f);
    float4 bzH = bzL;
    if (!CAT && bias) {
        bzL = *(const float4*)(bias + n0 + tn * 4);
        bzH = *(const float4*)(bias + n0 + 64 + tn * 4);
    }

    #pragma unroll
    for (int i = 0; i < 4; i++) {
        U2 u0, u1, u2, u3;
        u0.u = acc[i][0]; u1.u = acc[i][1];
        u2.u = acc[i][2]; u3.u = acc[i][3];
        float4 lo = make_float4(u0.f.x + bzL.x, u0.f.y + bzL.y,
                                u1.f.x + bzL.z, u1.f.y + bzL.w);
        float4 hi = make_float4(u2.f.x + bzH.x, u2.f.y + bzH.y,
                                u3.f.x + bzH.z, u3.f.y + bzH.w);
        float* crow = C + (size_t)(tm * 4 + i) * N + n0;
        *(float4*)(crow + tn * 4)      = lo;
        *(float4*)(crow + 64 + tn * 4) = hi;
    }
}

// ---------------- LSTM cell: sum split-K partials + elementwise --------
__global__ void __launch_bounds__(256) cell_kernel(
    const float* __restrict__ b_ih, const float* __restrict__ b_hh)
{
    int idx4 = blockIdx.x * blockDim.x + threadIdx.x;   // over BB*HH/4
    if (idx4 >= BB * HH / 4) return;
    int b  = idx4 >> 8;           // HH/4 = 256 quads per row
    int n  = (idx4 & 255) * 4;

    float4 gq[4];                  // i, f, g, o (each 4 lanes)
    #pragma unroll
    for (int q = 0; q < 4; q++) {
        float4 s = make_float4(0.f, 0.f, 0.f, 0.f);
        size_t off = (size_t)b * G4 + q * HH + n;
        #pragma unroll
        for (int p = 0; p < SPLITK; p++) {
            float4 v = *(const float4*)(&g_gp[p][off]);
            s.x += v.x; s.y += v.y; s.z += v.z; s.w += v.w;
        }
        float4 bi = *(const float4*)(b_ih + q * HH + n);
        float4 bh = *(const float4*)(b_hh + q * HH + n);
        s.x += bi.x + bh.x; s.y += bi.y + bh.y;
        s.z += bi.z + bh.z; s.w += bi.w + bh.w;
        gq[q] = s;
    }

    float4 c = *(const float4*)(&g_c[(size_t)b * HH + n]);
    float4 cn, hn;
    #pragma unroll
    for (int e = 0; e < 4; e++) {
        float ig = (&gq[0].x)[e];
        float fg = (&gq[1].x)[e];
        float gg = (&gq[2].x)[e];
        float og = (&gq[3].x)[e];
        float cv = (&c.x)[e];
        float si = 1.0f / (1.0f + expf(-ig));
        float sf = 1.0f / (1.0f + expf(-fg));
        float so = 1.0f / (1.0f + expf(-og));
        float cnew = sf * cv + si * tanhf(gg);
        (&cn.x)[e] = cnew;
        (&hn.x)[e] = so * tanhf(cnew);
    }
    *(float4*)(&g_c[(size_t)b * HH + n]) = cn;
    *(float4*)(&g_h[(size_t)b * HH + n]) = hn;
}

// ---------------- softmax + first-index argmax + output write ----------
__global__ void __launch_bounds__(1024) softmax_kernel(float* __restrict__ out, int t)
{
    const int b   = blockIdx.x;
    const int tid = threadIdx.x;
    const float4* lrow4 = (const float4*)(g_logits + (size_t)b * VV);
    const int NV4 = VV / 4;   // 8000

    __shared__ float smax[1024];
    __shared__ int   sidx[1024];
    __shared__ float ssum[1024];

    // pass 1: max with first-occurrence index
    float mx = -3.4e38f;
    int   mi = 0;
    for (int v = tid; v < NV4; v += 1024) {
        float4 l = lrow4[v];
        #pragma unroll
        for (int e = 0; e < 4; e++) {
            float le = (&l.x)[e];
            if (le > mx) { mx = le; mi = v * 4 + e; }
        }
    }
    smax[tid] = mx; sidx[tid] = mi;
    __syncthreads();
    for (int s = 512; s > 0; s >>= 1) {
        if (tid < s) {
            float om = smax[tid + s]; int oi = sidx[tid + s];
            if (om > smax[tid] || (om == smax[tid] && oi < sidx[tid])) {
                smax[tid] = om; sidx[tid] = oi;
            }
        }
        __syncthreads();
    }
    const float rowmax = smax[0];
    const int   pred   = sidx[0];

    // pass 2: sum of exp
    float acc = 0.0f;
    for (int v = tid; v < NV4; v += 1024) {
        float4 l = lrow4[v];
        acc += __expf(l.x - rowmax) + __expf(l.y - rowmax)
             + __expf(l.z - rowmax) + __expf(l.w - rowmax);
    }
    ssum[tid] = acc;
    __syncthreads();
    for (int s = 512; s > 0; s >>= 1) {
        if (tid < s) ssum[tid] += ssum[tid + s];
        __syncthreads();
    }
    const float inv = 1.0f / ssum[0];

    // pass 3: write probabilities out[b, t, :]
    float4* orow4 = (float4*)(out + ((size_t)b * TT + t) * VV);
    for (int v = tid; v < NV4; v += 1024) {
        float4 l = lrow4[v];
        float4 o;
        o.x = __expf(l.x - rowmax) * inv;
        o.y = __expf(l.y - rowmax) * inv;
        o.z = __expf(l.z - rowmax) * inv;
        o.w = __expf(l.w - rowmax) * inv;
        orow4[v] = o;
    }

    if (tid == 0) {
        g_last[b] = pred;
        out[(size_t)BB * TT * VV + (size_t)b * TT + t] = (float)pred;
    }
}

// ---------------- launch ------------------------------------------------
extern "C" void kernel_launch(void* const* d_in, const int* in_sizes, int n_in,
                              void* d_out, int out_size) {
    const float* hidden    = (const float*)d_in[0];
    const float* embedding = (const float*)d_in[1];
    const float* W_ih      = (const float*)d_in[2];
    const float* W_hh      = (const float*)d_in[3];
    const float* b_ih      = (const float*)d_in[4];
    const float* b_hh      = (const float*)d_in[5];
    const float* W_out     = (const float*)d_in[6];
    const float* b_out     = (const float*)d_in[7];
    float* out = (float*)d_out;

    float *pgp, *plog;
    cudaGetSymbolAddress((void**)&pgp,  g_gp);
    cudaGetSymbolAddress((void**)&plog, g_logits);

    init_kernel<<<(BB * HH + 255) / 256, 256>>>(hidden);

    for (int t = 0; t < TT; t++) {
        // gates: C_part[s] = A_cat[:, s*256:(s+1)*256] @ Wcat^T chunk
        gemm_kernel<true><<<dim3(G4 / BN, SPLITK), 256>>>(
            embedding, W_ih, W_hh, nullptr, pgp, G4, KC_GATES);

        cell_kernel<<<(BB * HH / 4 + 255) / 256, 256>>>(b_ih, b_hh);

        // logits: h @ W_out^T + b_out
        gemm_kernel<false><<<dim3(VV / BN, 1), 256>>>(
            embedding, W_out, nullptr, b_out, plog, VV, HH);

        softmax_kernel<<<BB, 1024>>>(out, t);
    }
}

// round 5
// speedup vs baseline: 1.7159x; 1.3395x over previous
#include <cuda_runtime.h>
#include <cstdint>
#include <math.h>

#define BB   64
#define HH   1024
#define ED   1024
#define VV   32000
#define TT   50
#define G4   4096
#define START_INDEX 1

#define BM 64
#define BN 256
#define BK 32
#define THR 128
#define SPLITK 8
#define KC_GATES ((2 * HH) / SPLITK)   // 256

#define SMEM_BYTES (2*BK*64*8 + 2*BK*BN*4)   // As2 double + Bs double = 96KB

typedef unsigned long long ull;

// ---------------- device-resident state (no allocations) ----------------
__device__ float g_h[BB * HH];
__device__ float g_c[BB * HH];
__device__ float g_gp[SPLITK][BB * G4];
__device__ float g_logits[(size_t)BB * VV];
__device__ int   g_last[BB];
__device__ float g_wt_out[(size_t)HH * VV];      // W_out^T : [1024][32000]
__device__ float g_wt_g[(size_t)(2*HH) * G4];    // [W_ih|W_hh]^T : [2048][4096]

// ---------------- init ---------------------------------------------------
__global__ void init_kernel(const float* __restrict__ hidden) {
    int i = blockIdx.x * blockDim.x + threadIdx.x;
    if (i < BB * HH) { g_h[i] = hidden[i]; g_c[i] = 0.0f; }
    if (i < BB) g_last[i] = START_INDEX;
}

// ---------------- transpose: dst[NCOLS][NROWS] = src[NROWS][NCOLS]^T -----
__global__ void transpose_kernel(float* __restrict__ dst,
                                 const float* __restrict__ src,
                                 int NROWS, int NCOLS) {
    __shared__ float tile[32][33];
    int n0 = blockIdx.x * 32;
    int k0 = blockIdx.y * 32;
    int tx = threadIdx.x & 31;
    int ty = threadIdx.x >> 5;       // 0..7
    #pragma unroll
    for (int j = 0; j < 4; j++)
        tile[ty + j * 8][tx] = src[(size_t)(n0 + ty + j * 8) * NCOLS + k0 + tx];
    __syncthreads();
    #pragma unroll
    for (int j = 0; j < 4; j++)
        dst[(size_t)(k0 + ty + j * 8) * NROWS + n0 + tx] = tile[tx][ty + j * 8];
}

// ---------------- packed f32x2 helpers -----------------------------------
__device__ __forceinline__ ull pk2(float x, float y) {
    ull r;
    asm("mov.b64 %0, {%1, %2};" : "=l"(r) : "f"(x), "f"(y));
    return r;
}
__device__ __forceinline__ void ffma2(ull& d, ull a, ull b) {
    asm("fma.rn.f32x2 %0, %1, %2, %0;" : "+l"(d) : "l"(a), "l"(b));
}
union U2 { ull u; float2 f; };

__device__ __forceinline__ void cpa16(unsigned int dst, const float* src) {
    asm volatile("cp.async.cg.shared.global [%0], [%1], 16;\n" :: "r"(dst), "l"(src));
}
__device__ __forceinline__ void cpa_commit() {
    asm volatile("cp.async.commit_group;\n" ::: "memory");
}

// ---------------- GEMM v3: C[64 x N] = A[64 x K] @ Wt[K x N] -------------
// 128 threads. BM=64, BN=256, BK=32. Per-thread: 8 rows x 16 cols
// (4 chunks of 4 cols at c*64+tn*4). 8 A-ull x 8 B-ull -> 64 FFMA2 per kk
// per thread from 8 LDS.128: crossbar/FMA balanced 1:1.
// B staged via cp.async from pre-transposed weights; A splatted via LDG+STS.
template<bool CAT>
__global__ void __launch_bounds__(THR) gemm3_kernel(
    const float* __restrict__ emb,
    const float* __restrict__ wt,    // [K][N] transposed weights
    const float* __restrict__ bias,
    float* __restrict__ Cout,
    int N, int Kc)
{
    extern __shared__ char dynsmem[];
    ull*   As2 = (ull*)dynsmem;                       // [2][BK][64]
    float* Bs  = (float*)(dynsmem + 2 * BK * 64 * 8); // [2][BK][BN]

    const int t  = threadIdx.x;
    const int n0 = blockIdx.x * BN;
    const int kbase = CAT ? blockIdx.y * Kc : 0;
    float* C = Cout + (CAT ? (size_t)blockIdx.y * BM * N : 0);

    // ---- A staging mapping: thread t stages row m = t>>1, k-half (t&1)*16
    const int am   = t >> 1;
    const int koff = (t & 1) * 16;
    const float* abase;
    if (CAT) {
        if (kbase < HH) abase = emb + (size_t)g_last[am] * ED + kbase;
        else            abase = g_h + (size_t)am * HH + (kbase - HH);
    } else {
        abase = g_h + (size_t)am * HH;
    }
    abase += koff;

    // ---- compute mapping ----
    const int tn = t & 15;     // col group
    const int tm = t >> 4;     // row group (0..7), rows tm*8..+7

    ull acc[8][8];
    #pragma unroll
    for (int i = 0; i < 8; i++)
        #pragma unroll
        for (int j = 0; j < 8; j++) acc[i][j] = 0ull;

    const int NT = Kc / BK;

    // ---- helpers as lambdas ----
    auto stageB = [&](int s, int k0) {
        unsigned int dstBase =
            (unsigned int)__cvta_generic_to_shared(Bs + (size_t)s * BK * BN);
        const float* wsrc = wt + (size_t)(kbase + k0) * N + n0;
        #pragma unroll
        for (int i = 0; i < 16; i++) {
            int seg = t + i * THR;
            int row = seg >> 6;        // 64 segs per k-row (256 floats)
            int cs  = seg & 63;
            cpa16(dstBase + (unsigned int)(row * BN + cs * 4) * 4,
                  wsrc + (size_t)row * N + cs * 4);
        }
        cpa_commit();
    };
    auto stsA = [&](int s, const float4* av) {
        #pragma unroll
        for (int q = 0; q < 4; q++) {
            const float* f = &av[q].x;
            #pragma unroll
            for (int e = 0; e < 4; e++) {
                int k = koff + q * 4 + e;
                As2[((size_t)s * BK + k) * 64 + am] = pk2(f[e], f[e]);
            }
        }
    };

    // ---- prologue: stage tile 0 ----
    {
        float4 av[4];
        #pragma unroll
        for (int q = 0; q < 4; q++) av[q] = *(const float4*)(abase + q * 4);
        stsA(0, av);
        stageB(0, 0);
    }

    float4 avn[4];
    for (int tile = 0; tile < NT; tile++) {
        const int s = tile & 1;
        const bool have = (tile + 1 < NT);
        if (have) {
            stageB(s ^ 1, (tile + 1) * BK);
            const float* ap = abase + (tile + 1) * BK;
            #pragma unroll
            for (int q = 0; q < 4; q++) avn[q] = *(const float4*)(ap + q * 4);
            asm volatile("cp.async.wait_group 1;\n" ::: "memory");
        } else {
            asm volatile("cp.async.wait_group 0;\n" ::: "memory");
        }
        __syncthreads();

        // ---- compute BK k-steps on buffer s ----
        const ull*   Abuf = As2 + (size_t)s * BK * 64 + tm * 8;
        const float* Bbuf = Bs  + (size_t)s * BK * BN + tn * 4;
        #pragma unroll 8
        for (int kk = 0; kk < BK; kk++) {
            const ull*   ar = Abuf + (size_t)kk * 64;
            const float* br = Bbuf + (size_t)kk * BN;
            ulonglong2 A0 = *(const ulonglong2*)(ar + 0);
            ulonglong2 A1 = *(const ulonglong2*)(ar + 2);
            ulonglong2 A2 = *(const ulonglong2*)(ar + 4);
            ulonglong2 A3 = *(const ulonglong2*)(ar + 6);
            ulonglong2 B0 = *(const ulonglong2*)(br + 0);
            ulonglong2 B1 = *(const ulonglong2*)(br + 64);
            ulonglong2 B2 = *(const ulonglong2*)(br + 128);
            ulonglong2 B3 = *(const ulonglong2*)(br + 192);
#define GROW(i, av) \
            ffma2(acc[i][0], av, B0.x); ffma2(acc[i][1], av, B0.y); \
            ffma2(acc[i][2], av, B1.x); ffma2(acc[i][3], av, B1.y); \
            ffma2(acc[i][4], av, B2.x); ffma2(acc[i][5], av, B2.y); \
            ffma2(acc[i][6], av, B3.x); ffma2(acc[i][7], av, B3.y);
            GROW(0, A0.x) GROW(1, A0.y) GROW(2, A1.x) GROW(3, A1.y)
            GROW(4, A2.x) GROW(5, A2.y) GROW(6, A3.x) GROW(7, A3.y)
#undef GROW
        }

        if (have) stsA(s ^ 1, avn);
        __syncthreads();
    }

    // ---- epilogue ----
    float4 bz[4];
    #pragma unroll
    for (int c = 0; c < 4; c++) {
        if (!CAT && bias) bz[c] = *(const float4*)(bias + n0 + c * 64 + tn * 4);
        else              bz[c] = make_float4(0.f, 0.f, 0.f, 0.f);
    }
    #pragma unroll
    for (int i = 0; i < 8; i++) {
        float* crow = C + (size_t)(tm * 8 + i) * N + n0 + tn * 4;
        #pragma unroll
        for (int c = 0; c < 4; c++) {
            U2 lo, hi;
            lo.u = acc[i][2 * c];
            hi.u = acc[i][2 * c + 1];
            float4 v = make_float4(lo.f.x + bz[c].x, lo.f.y + bz[c].y,
                                   hi.f.x + bz[c].z, hi.f.y + bz[c].w);
            *(float4*)(crow + c * 64) = v;
        }
    }
}

// ---------------- LSTM cell: sum split-K partials + elementwise ----------
__global__ void __launch_bounds__(256) cell_kernel(
    const float* __restrict__ b_ih, const float* __restrict__ b_hh)
{
    int idx4 = blockIdx.x * blockDim.x + threadIdx.x;
    if (idx4 >= BB * HH / 4) return;
    int b = idx4 >> 8;
    int n = (idx4 & 255) * 4;

    float4 gq[4];
    #pragma unroll
    for (int q = 0; q < 4; q++) {
        float4 s = make_float4(0.f, 0.f, 0.f, 0.f);
        size_t off = (size_t)b * G4 + q * HH + n;
        #pragma unroll
        for (int p = 0; p < SPLITK; p++) {
            float4 v = *(const float4*)(&g_gp[p][off]);
            s.x += v.x; s.y += v.y; s.z += v.z; s.w += v.w;
        }
        float4 bi = *(const float4*)(b_ih + q * HH + n);
        float4 bh = *(const float4*)(b_hh + q * HH + n);
        s.x += bi.x + bh.x; s.y += bi.y + bh.y;
        s.z += bi.z + bh.z; s.w += bi.w + bh.w;
        gq[q] = s;
    }

    float4 c = *(const float4*)(&g_c[(size_t)b * HH + n]);
    float4 cn, hn;
    #pragma unroll
    for (int e = 0; e < 4; e++) {
        float ig = (&gq[0].x)[e];
        float fg = (&gq[1].x)[e];
        float gg = (&gq[2].x)[e];
        float og = (&gq[3].x)[e];
        float cv = (&c.x)[e];
        float si = 1.0f / (1.0f + expf(-ig));
        float sf = 1.0f / (1.0f + expf(-fg));
        float so = 1.0f / (1.0f + expf(-og));
        float cnew = sf * cv + si * tanhf(gg);
        (&cn.x)[e] = cnew;
        (&hn.x)[e] = so * tanhf(cnew);
    }
    *(float4*)(&g_c[(size_t)b * HH + n]) = cn;
    *(float4*)(&g_h[(size_t)b * HH + n]) = hn;
}

// ---------------- softmax + first-index argmax + output write ------------
__global__ void __launch_bounds__(1024) softmax_kernel(float* __restrict__ out, int t)
{
    const int b   = blockIdx.x;
    const int tid = threadIdx.x;
    const float4* lrow4 = (const float4*)(g_logits + (size_t)b * VV);
    const int NV4 = VV / 4;

    __shared__ float smax[1024];
    __shared__ int   sidx[1024];
    __shared__ float ssum[1024];

    float mx = -3.4e38f;
    int   mi = 0;
    for (int v = tid; v < NV4; v += 1024) {
        float4 l = lrow4[v];
        #pragma unroll
        for (int e = 0; e < 4; e++) {
            float le = (&l.x)[e];
            if (le > mx) { mx = le; mi = v * 4 + e; }
        }
    }
    smax[tid] = mx; sidx[tid] = mi;
    __syncthreads();
    for (int s = 512; s > 0; s >>= 1) {
        if (tid < s) {
            float om = smax[tid + s]; int oi = sidx[tid + s];
            if (om > smax[tid] || (om == smax[tid] && oi < sidx[tid])) {
                smax[tid] = om; sidx[tid] = oi;
            }
        }
        __syncthreads();
    }
    const float rowmax = smax[0];
    const int   pred   = sidx[0];

    float acc = 0.0f;
    for (int v = tid; v < NV4; v += 1024) {
        float4 l = lrow4[v];
        acc += __expf(l.x - rowmax) + __expf(l.y - rowmax)
             + __expf(l.z - rowmax) + __expf(l.w - rowmax);
    }
    ssum[tid] = acc;
    __syncthreads();
    for (int s = 512; s > 0; s >>= 1) {
        if (tid < s) ssum[tid] += ssum[tid + s];
        __syncthreads();
    }
    const float inv = 1.0f / ssum[0];

    float4* orow4 = (float4*)(out + ((size_t)b * TT + t) * VV);
    for (int v = tid; v < NV4; v += 1024) {
        float4 l = lrow4[v];
        float4 o;
        o.x = __expf(l.x - rowmax) * inv;
        o.y = __expf(l.y - rowmax) * inv;
        o.z = __expf(l.z - rowmax) * inv;
        o.w = __expf(l.w - rowmax) * inv;
        orow4[v] = o;
    }

    if (tid == 0) {
        g_last[b] = pred;
        out[(size_t)BB * TT * VV + (size_t)b * TT + t] = (float)pred;
    }
}

// ---------------- launch --------------------------------------------------
extern "C" void kernel_launch(void* const* d_in, const int* in_sizes, int n_in,
                              void* d_out, int out_size) {
    const float* hidden    = (const float*)d_in[0];
    const float* embedding = (const float*)d_in[1];
    const float* W_ih      = (const float*)d_in[2];
    const float* W_hh      = (const float*)d_in[3];
    const float* b_ih      = (const float*)d_in[4];
    const float* b_hh      = (const float*)d_in[5];
    const float* W_out     = (const float*)d_in[6];
    const float* b_out     = (const float*)d_in[7];
    float* out = (float*)d_out;

    float *pgp, *plog, *pwtout, *pwtg;
    cudaGetSymbolAddress((void**)&pgp,    g_gp);
    cudaGetSymbolAddress((void**)&plog,   g_logits);
    cudaGetSymbolAddress((void**)&pwtout, g_wt_out);
    cudaGetSymbolAddress((void**)&pwtg,   g_wt_g);

    // host-side attribute setup — not a graph node
    cudaFuncSetAttribute(gemm3_kernel<true>,
                         cudaFuncAttributeMaxDynamicSharedMemorySize, SMEM_BYTES);
    cudaFuncSetAttribute(gemm3_kernel<false>,
                         cudaFuncAttributeMaxDynamicSharedMemorySize, SMEM_BYTES);

    // pre-transpose weights (once per graph replay, ~50us amortized)
    transpose_kernel<<<dim3(VV / 32, HH / 32), 256>>>(pwtout, W_out, VV, HH);
    transpose_kernel<<<dim3(G4 / 32, HH / 32), 256>>>(pwtg, W_ih, G4, HH);
    transpose_kernel<<<dim3(G4 / 32, HH / 32), 256>>>(
        pwtg + (size_t)HH * G4, W_hh, G4, HH);

    init_kernel<<<(BB * HH + 255) / 256, 256>>>(hidden);

    for (int t = 0; t < TT; t++) {
        // gates: split-K over 8 chunks of K=256 from [W_ih|W_hh]^T
        gemm3_kernel<true><<<dim3(G4 / BN, SPLITK), THR, SMEM_BYTES>>>(
            embedding, pwtg, nullptr, pgp, G4, KC_GATES);

        cell_kernel<<<(BB * HH / 4 + 255) / 256, 256>>>(b_ih, b_hh);

        // logits: h @ W_out^T + b_out  (K=1024)
        gemm3_kernel<false><<<dim3(VV / BN, 1), THR, SMEM_BYTES>>>(
            embedding, pwtout, b_out, plog, VV, HH);

        softmax_kernel<<<BB, 1024>>>(out, t);
    }
}